// round 6
// baseline (speedup 1.0000x reference)
#include <cuda_runtime.h>
#include <cstdint>

// SNN: x[B,5] -> L1(32) -> spike(dot>=2) -> L2(32) -> L3(16) -> L4(10) -> spike.
// Warp-cooperative layer 1: lane j owns neuron j (W1 row j in 5 registers,
// loaded once per block). Per data row: LDS.128 broadcast of x (4 rows/load),
// 5-FMA dot per lane, mask1 = ballot. Layers 2-4 provably all-zero unless
// popc(mask1) >= g_minpop (sound bound, validated rel_err==0 in R3-R5);
// rare path (~1e-4 of rows) runs warp-parallel with ballots between layers.

__device__ int g_minpop;

__global__ void setup_kernel(const float* __restrict__ W2) {
    int i = threadIdx.x;
    float mx = W2[i];
    #pragma unroll
    for (int j = 1; j < 32; j++) mx = fmaxf(mx, W2[j * 32 + i]);
    #pragma unroll
    for (int s = 16; s > 0; s >>= 1)
        mx = fmaxf(mx, __shfl_xor_sync(0xffffffffu, mx, s));
    if (i == 0) {
        int mp = 1;  // smallest popc whose bound popc*cmax could round to >= 2
        while (mp < 33 && (float)mp * mx < 1.99f) mp++;
        g_minpop = mp;
    }
}

// Warp-parallel exact layers 2-4. Lane j = output neuron j; per-layer sums in
// increasing-i order (identical arithmetic to the R1-R5 validated rare path).
__device__ __noinline__ void rare_warp(unsigned m1, float* __restrict__ orow,
                                       int lane,
                                       const float* __restrict__ W2,
                                       const float* __restrict__ W3,
                                       const float* __restrict__ W4)
{
    float a2 = 0.0f;
    unsigned mm = m1;
    while (mm) { int i = __ffs(mm) - 1; mm &= mm - 1; a2 += W2[lane * 32 + i]; }
    unsigned m2 = __ballot_sync(0xffffffffu, a2 >= 2.0f);
    if (!m2) return;

    const int l3 = (lane < 16) ? lane : 0;   // keep loop warp-uniform
    float a3 = 0.0f;
    mm = m2;
    while (mm) { int i = __ffs(mm) - 1; mm &= mm - 1; a3 += W3[l3 * 32 + i]; }
    unsigned m3 = __ballot_sync(0xffffffffu, (lane < 16) && (a3 >= 2.0f));
    if (!m3) return;

    const int l4 = (lane < 10) ? lane : 0;
    float a4 = 0.0f;
    mm = m3;
    while (mm) { int i = __ffs(mm) - 1; mm &= mm - 1; a4 += W4[l4 * 16 + i]; }
    if (lane < 10) orow[lane] = (a4 >= 2.0f) ? 1.0f : 0.0f;  // zeros already filled
}

#define BT  256          // 8 warps
#define RPB 512          // rows per block
#define RPW (RPB / 8)    // 64 rows per warp

__global__ __launch_bounds__(BT)
void snn_kernel(const float* __restrict__ x,
                const float* __restrict__ W1,
                const float* __restrict__ W2,
                const float* __restrict__ W3,
                const float* __restrict__ W4,
                float* __restrict__ out)
{
    __shared__ float sXT[5][RPB];   // x transposed: sXT[k][row]

    const int tid  = threadIdx.x;
    const int lane = tid & 31;
    const int wid  = tid >> 5;
    const size_t rowbase = (size_t)blockIdx.x * RPB;
    const int mp = g_minpop;

    // lane j's neuron weights (same in every warp) — once per block
    const float w0 = __ldg(&W1[lane * 5 + 0]);
    const float w1 = __ldg(&W1[lane * 5 + 1]);
    const float w2 = __ldg(&W1[lane * 5 + 2]);
    const float w3 = __ldg(&W1[lane * 5 + 3]);
    const float w4 = __ldg(&W1[lane * 5 + 4]);

    // stage x tile transposed (coalesced LDG.128, scattered STS.32)
    {
        const float4* xv = reinterpret_cast<const float4*>(x + rowbase * 5);
        #pragma unroll
        for (int i = tid; i < RPB * 5 / 4; i += BT) {
            float4 v = xv[i];
            int e = 4 * i;
            sXT[e % 5][e / 5] = v.x;
            sXT[(e + 1) % 5][(e + 1) / 5] = v.y;
            sXT[(e + 2) % 5][(e + 2) / 5] = v.z;
            sXT[(e + 3) % 5][(e + 3) / 5] = v.w;
        }
    }
    // zero-fill this block's output tile (coalesced STG.128); rare writes
    // after __syncthreads overwrite the handful of nonzero rows.
    {
        float4* ov = reinterpret_cast<float4*>(out + rowbase * 10);
        const float4 z = make_float4(0.f, 0.f, 0.f, 0.f);
        #pragma unroll
        for (int i = tid; i < RPB * 10 / 4; i += BT) ov[i] = z;
    }
    __syncthreads();

    const int rbeg = wid * RPW;
    #pragma unroll 2
    for (int r0 = 0; r0 < RPW; r0 += 4) {
        const int r = rbeg + r0;

        // 4 rows per iteration; x via LDS.128 broadcast, consumed immediately
        float d0, d1, d2, d3;
        {
            float4 t = *reinterpret_cast<const float4*>(&sXT[0][r]);
            d0 = w0 * t.x; d1 = w0 * t.y; d2 = w0 * t.z; d3 = w0 * t.w;
        }
        {
            float4 t = *reinterpret_cast<const float4*>(&sXT[1][r]);
            d0 = fmaf(w1, t.x, d0); d1 = fmaf(w1, t.y, d1);
            d2 = fmaf(w1, t.z, d2); d3 = fmaf(w1, t.w, d3);
        }
        {
            float4 t = *reinterpret_cast<const float4*>(&sXT[2][r]);
            d0 = fmaf(w2, t.x, d0); d1 = fmaf(w2, t.y, d1);
            d2 = fmaf(w2, t.z, d2); d3 = fmaf(w2, t.w, d3);
        }
        {
            float4 t = *reinterpret_cast<const float4*>(&sXT[3][r]);
            d0 = fmaf(w3, t.x, d0); d1 = fmaf(w3, t.y, d1);
            d2 = fmaf(w3, t.z, d2); d3 = fmaf(w3, t.w, d3);
        }
        {
            float4 t = *reinterpret_cast<const float4*>(&sXT[4][r]);
            d0 = fmaf(w4, t.x, d0); d1 = fmaf(w4, t.y, d1);
            d2 = fmaf(w4, t.z, d2); d3 = fmaf(w4, t.w, d3);
        }

        const unsigned m0 = __ballot_sync(0xffffffffu, d0 >= 2.0f);
        const unsigned m1 = __ballot_sync(0xffffffffu, d1 >= 2.0f);
        const unsigned m2 = __ballot_sync(0xffffffffu, d2 >= 2.0f);
        const unsigned m3 = __ballot_sync(0xffffffffu, d3 >= 2.0f);

        const bool h0 = __popc(m0) >= mp;
        const bool h1 = __popc(m1) >= mp;
        const bool h2 = __popc(m2) >= mp;
        const bool h3 = __popc(m3) >= mp;
        if (h0 | h1 | h2 | h3) {   // warp-uniform, ~1e-4 taken
            float* orow = out + (rowbase + r) * 10;
            if (h0) rare_warp(m0, orow,      lane, W2, W3, W4);
            if (h1) rare_warp(m1, orow + 10, lane, W2, W3, W4);
            if (h2) rare_warp(m2, orow + 20, lane, W2, W3, W4);
            if (h3) rare_warp(m3, orow + 30, lane, W2, W3, W4);
        }
    }
}

extern "C" void kernel_launch(void* const* d_in, const int* in_sizes, int n_in,
                              void* d_out, int out_size)
{
    const float* x  = (const float*)d_in[0];
    const float* W1 = (const float*)d_in[1];
    const float* W2 = (const float*)d_in[2];
    const float* W3 = (const float*)d_in[3];
    const float* W4 = (const float*)d_in[4];
    float* out = (float*)d_out;

    const int B = in_sizes[0] / 5;        // 2097152
    const int grid = B / RPB;             // 4096

    setup_kernel<<<1, 32>>>(W2);
    snn_kernel<<<grid, BT>>>(x, W1, W2, W3, W4, out);
}

// round 7
// speedup vs baseline: 1.4294x; 1.4294x over previous
#include <cuda_runtime.h>
#include <cstdint>

// SNN: x[B,5] -> L1(32) -> spike(dot>=2) -> L2(32) -> L3(16) -> L4(10) -> spike.
// R2 layout (1 row/thread, LDS.128 weight broadcasts) with overheads removed:
// direct __ldg x reads, zero-fill + rare scatter output, popc gate, one sync.

__device__ int g_minpop;

__global__ void setup_kernel(const float* __restrict__ W2) {
    int i = threadIdx.x;
    float mx = W2[i];
    #pragma unroll
    for (int j = 1; j < 32; j++) mx = fmaxf(mx, W2[j * 32 + i]);
    #pragma unroll
    for (int s = 16; s > 0; s >>= 1)
        mx = fmaxf(mx, __shfl_xor_sync(0xffffffffu, mx, s));
    if (i == 0) {
        int mp = 1;  // smallest popc whose bound popc*cmax could round to >= 2
        while (mp < 33 && (float)mp * mx < 1.99f) mp++;
        g_minpop = mp;
    }
}

// exact layers 2-4 (rare, ~1e-4 of rows); identical to R1-R6 validated code.
__device__ __noinline__ unsigned rare_path(unsigned mask1,
                                           const float* __restrict__ W2,
                                           const float* __restrict__ W3,
                                           const float* __restrict__ W4)
{
    unsigned mask2 = 0;
    #pragma unroll
    for (int jc = 0; jc < 32; jc += 8) {
        float acc[8] = {0, 0, 0, 0, 0, 0, 0, 0};
        unsigned mm = mask1;
        while (mm) {
            int i = __ffs(mm) - 1; mm &= mm - 1;
            #pragma unroll
            for (int j = 0; j < 8; j++) acc[j] += W2[(jc + j) * 32 + i];
        }
        #pragma unroll
        for (int j = 0; j < 8; j++)
            if (acc[j] >= 2.0f) mask2 |= 1u << (jc + j);
    }
    if (!mask2) return 0;

    unsigned mask3 = 0;
    #pragma unroll
    for (int jc = 0; jc < 16; jc += 8) {
        float acc[8] = {0, 0, 0, 0, 0, 0, 0, 0};
        unsigned mm = mask2;
        while (mm) {
            int i = __ffs(mm) - 1; mm &= mm - 1;
            #pragma unroll
            for (int j = 0; j < 8; j++) acc[j] += W3[(jc + j) * 32 + i];
        }
        #pragma unroll
        for (int j = 0; j < 8; j++)
            if (acc[j] >= 2.0f) mask3 |= 1u << (jc + j);
    }
    if (!mask3) return 0;

    float acc4[10];
    #pragma unroll
    for (int j = 0; j < 10; j++) acc4[j] = 0.0f;
    unsigned mm = mask3;
    while (mm) {
        int i = __ffs(mm) - 1; mm &= mm - 1;
        #pragma unroll
        for (int j = 0; j < 10; j++) acc4[j] += W4[j * 16 + i];
    }
    unsigned om = 0;
    #pragma unroll
    for (int j = 0; j < 10; j++)
        if (acc4[j] >= 2.0f) om |= 1u << j;
    return om;
}

#define BT 256

__global__ __launch_bounds__(BT)
void snn_kernel(const float* __restrict__ x,
                const float* __restrict__ W1,
                const float* __restrict__ W2,
                const float* __restrict__ W3,
                const float* __restrict__ W4,
                float* __restrict__ out)
{
    __shared__ float sW1[160];

    const int tid = threadIdx.x;
    const size_t row = (size_t)blockIdx.x * BT + tid;
    const int mp = g_minpop;

    // stage W1 (40 float4)
    if (tid < 40)
        reinterpret_cast<float4*>(sW1)[tid] =
            reinterpret_cast<const float4*>(W1)[tid];

    // zero-fill this block's output tile: 640 coalesced STG.128.
    // Rare scatter after the single __syncthreads overwrites nonzero rows.
    {
        float4* ov = reinterpret_cast<float4*>(out + (size_t)blockIdx.x * (BT * 10));
        const float4 z = make_float4(0.f, 0.f, 0.f, 0.f);
        #pragma unroll
        for (int i = tid; i < BT * 10 / 4; i += BT) ov[i] = z;
    }

    // direct x reads: warp's 5 LDG.32 each span 640 contiguous bytes
    const float* xr = x + row * 5;
    const float x0 = __ldg(xr + 0);
    const float x1 = __ldg(xr + 1);
    const float x2 = __ldg(xr + 2);
    const float x3 = __ldg(xr + 3);
    const float x4 = __ldg(xr + 4);

    __syncthreads();   // sW1 ready; all zero-fill STGs ordered before scatter

    // Layer 1: dense 32x5 via LDS.128 broadcasts (R2-validated order)
    unsigned mask1 = 0;
    const float4* w4 = reinterpret_cast<const float4*>(sW1);
    #pragma unroll
    for (int c = 0; c < 8; c++) {
        float w[20];
        #pragma unroll
        for (int q = 0; q < 5; q++) {
            float4 t = w4[c * 5 + q];
            w[q * 4 + 0] = t.x; w[q * 4 + 1] = t.y;
            w[q * 4 + 2] = t.z; w[q * 4 + 3] = t.w;
        }
        #pragma unroll
        for (int r = 0; r < 4; r++) {
            float a = w[r * 5 + 0] * x0;
            a = fmaf(w[r * 5 + 1], x1, a);
            a = fmaf(w[r * 5 + 2], x2, a);
            a = fmaf(w[r * 5 + 3], x3, a);
            a = fmaf(w[r * 5 + 4], x4, a);
            if (a >= 2.0f) mask1 |= 1u << (4 * c + r);
        }
    }

    // gate (~1e-4 taken); rare path exact
    if (__popc(mask1) >= mp) {
        unsigned om = rare_path(mask1, W2, W3, W4);
        if (om) {
            float* o = out + row * 10;
            #pragma unroll
            for (int j = 0; j < 10; j++)
                o[j] = ((om >> j) & 1u) ? 1.0f : 0.0f;
        }
    }
}

extern "C" void kernel_launch(void* const* d_in, const int* in_sizes, int n_in,
                              void* d_out, int out_size)
{
    const float* x  = (const float*)d_in[0];
    const float* W1 = (const float*)d_in[1];
    const float* W2 = (const float*)d_in[2];
    const float* W3 = (const float*)d_in[3];
    const float* W4 = (const float*)d_in[4];
    float* out = (float*)d_out;

    const int B = in_sizes[0] / 5;        // 2097152
    const int grid = B / BT;              // 8192

    setup_kernel<<<1, 32>>>(W2);
    snn_kernel<<<grid, BT>>>(x, W1, W2, W3, W4, out);
}

// round 8
// speedup vs baseline: 1.5462x; 1.0817x over previous
#include <cuda_runtime.h>
#include <cstdint>

// SNN: x[B,5] -> L1(32) -> spike(dot>=2) -> L2(32) -> L3(16) -> L4(10) -> spike.
// W1 lives in __constant__ memory: warp-uniform LDCU on the const port, zero
// L1tex traffic for weights. 1 row/thread, direct x LDG, zero-fill + rare
// scatter output, popc gate (sound bound, rel_err==0 in R3-R7).

__constant__ float cW1[160];
__device__ int g_minpop;

__global__ void setup_kernel(const float* __restrict__ W2) {
    int i = threadIdx.x;
    float mx = W2[i];
    #pragma unroll
    for (int j = 1; j < 32; j++) mx = fmaxf(mx, W2[j * 32 + i]);
    #pragma unroll
    for (int s = 16; s > 0; s >>= 1)
        mx = fmaxf(mx, __shfl_xor_sync(0xffffffffu, mx, s));
    if (i == 0) {
        int mp = 1;  // smallest popc whose bound popc*cmax could round to >= 2
        while (mp < 33 && (float)mp * mx < 1.99f) mp++;
        g_minpop = mp;
    }
}

// exact layers 2-4 (rare, ~1e-4 of rows); identical to R1-R7 validated code.
__device__ __noinline__ unsigned rare_path(unsigned mask1,
                                           const float* __restrict__ W2,
                                           const float* __restrict__ W3,
                                           const float* __restrict__ W4)
{
    unsigned mask2 = 0;
    #pragma unroll
    for (int jc = 0; jc < 32; jc += 8) {
        float acc[8] = {0, 0, 0, 0, 0, 0, 0, 0};
        unsigned mm = mask1;
        while (mm) {
            int i = __ffs(mm) - 1; mm &= mm - 1;
            #pragma unroll
            for (int j = 0; j < 8; j++) acc[j] += W2[(jc + j) * 32 + i];
        }
        #pragma unroll
        for (int j = 0; j < 8; j++)
            if (acc[j] >= 2.0f) mask2 |= 1u << (jc + j);
    }
    if (!mask2) return 0;

    unsigned mask3 = 0;
    #pragma unroll
    for (int jc = 0; jc < 16; jc += 8) {
        float acc[8] = {0, 0, 0, 0, 0, 0, 0, 0};
        unsigned mm = mask2;
        while (mm) {
            int i = __ffs(mm) - 1; mm &= mm - 1;
            #pragma unroll
            for (int j = 0; j < 8; j++) acc[j] += W3[(jc + j) * 32 + i];
        }
        #pragma unroll
        for (int j = 0; j < 8; j++)
            if (acc[j] >= 2.0f) mask3 |= 1u << (jc + j);
    }
    if (!mask3) return 0;

    float acc4[10];
    #pragma unroll
    for (int j = 0; j < 10; j++) acc4[j] = 0.0f;
    unsigned mm = mask3;
    while (mm) {
        int i = __ffs(mm) - 1; mm &= mm - 1;
        #pragma unroll
        for (int j = 0; j < 10; j++) acc4[j] += W4[j * 16 + i];
    }
    unsigned om = 0;
    #pragma unroll
    for (int j = 0; j < 10; j++)
        if (acc4[j] >= 2.0f) om |= 1u << j;
    return om;
}

#define BT 256

__global__ __launch_bounds__(BT)
void snn_kernel(const float* __restrict__ x,
                const float* __restrict__ W2,
                const float* __restrict__ W3,
                const float* __restrict__ W4,
                float* __restrict__ out)
{
    const int tid = threadIdx.x;
    const size_t row = (size_t)blockIdx.x * BT + tid;
    const int mp = g_minpop;

    // zero-fill this block's output tile: coalesced STG.128, fire-and-forget.
    {
        float4* ov = reinterpret_cast<float4*>(out + (size_t)blockIdx.x * (BT * 10));
        const float4 z = make_float4(0.f, 0.f, 0.f, 0.f);
        #pragma unroll
        for (int i = tid; i < BT * 10 / 4; i += BT) ov[i] = z;
    }

    // direct x reads (latency overlaps the barrier + const loads)
    const float* xr = x + row * 5;
    const float x0 = __ldg(xr + 0);
    const float x1 = __ldg(xr + 1);
    const float x2 = __ldg(xr + 2);
    const float x3 = __ldg(xr + 3);
    const float x4 = __ldg(xr + 4);

    __syncthreads();   // order zero-fill STGs before the rare scatter below

    // Layer 1: dense 32x5, weights from __constant__ (uniform LDCU, no L1).
    // Same mul->fma order as the reference-validated R2/R7 kernels.
    unsigned mask1 = 0;
    #pragma unroll
    for (int o = 0; o < 32; o++) {
        float a = cW1[o * 5 + 0] * x0;
        a = fmaf(cW1[o * 5 + 1], x1, a);
        a = fmaf(cW1[o * 5 + 2], x2, a);
        a = fmaf(cW1[o * 5 + 3], x3, a);
        a = fmaf(cW1[o * 5 + 4], x4, a);
        if (a >= 2.0f) mask1 |= 1u << o;
    }

    // gate (~1e-4 taken); rare path exact
    if (__popc(mask1) >= mp) {
        unsigned om = rare_path(mask1, W2, W3, W4);
        if (om) {
            float* o = out + row * 10;
            #pragma unroll
            for (int j = 0; j < 10; j++)
                o[j] = ((om >> j) & 1u) ? 1.0f : 0.0f;
        }
    }
}

extern "C" void kernel_launch(void* const* d_in, const int* in_sizes, int n_in,
                              void* d_out, int out_size)
{
    const float* x  = (const float*)d_in[0];
    const float* W1 = (const float*)d_in[1];
    const float* W2 = (const float*)d_in[2];
    const float* W3 = (const float*)d_in[3];
    const float* W4 = (const float*)d_in[4];
    float* out = (float*)d_out;

    const int B = in_sizes[0] / 5;        // 2097152
    const int grid = B / BT;              // 8192

    // D2D async copy into constant bank (graph-capturable, no allocation)
    cudaMemcpyToSymbolAsync(cW1, W1, 160 * sizeof(float), 0,
                            cudaMemcpyDeviceToDevice, 0);
    setup_kernel<<<1, 32>>>(W2);
    snn_kernel<<<grid, BT>>>(x, W2, W3, W4, out);
}